// round 6
// baseline (speedup 1.0000x reference)
#include <cuda_runtime.h>

// Shapes (fixed by the problem)
#define B_       32
#define QL       4
#define KVLEN    4096
#define HQ       32
#define HKV      8
#define D_       128
#define G_       4
#define ROWS     16                 // G_*QL query rows per (b, h_kv)
#define TILE     256
#define NTILES   (KVLEN / TILE)     // 16
#define NTHREADS 256
#define BOUND    (KVLEN - QL)       // 4092: ki >= BOUND comes from new key/value

typedef unsigned long long u64;

// Packed fp32x2 FMA (sm_100+): 2 MACs per issue slot, 2x scalar FFMA rate.
__device__ __forceinline__ void fma2(u64 &acc, u64 a, u64 b) {
    asm("fma.rn.f32x2 %0, %1, %2, %0;" : "+l"(acc) : "l"(a), "l"(b));
}
__device__ __forceinline__ float2 u2f(u64 v) {
    float2 r; asm("mov.b64 {%0,%1}, %2;" : "=f"(r.x), "=f"(r.y) : "l"(v)); return r;
}
__device__ __forceinline__ u64 f2u(float x, float y) {
    u64 r; asm("mov.b64 %0, {%1,%2};" : "=l"(r) : "f"(x), "f"(y)); return r;
}

__global__ __launch_bounds__(NTHREADS, 2)
void attn_decode_kernel(const float* __restrict__ query,
                        const float* __restrict__ keyn,
                        const float* __restrict__ valn,
                        const float* __restrict__ kcache,
                        const float* __restrict__ vcache,
                        const int*   __restrict__ btab,
                        float*       __restrict__ out)
{
    __shared__ __align__(16) float Q_s[ROWS][D_];        // 8 KB
    __shared__ __align__(16) float P_s[TILE][20];        // padded row (fewer STS conflicts), 20 KB
    __shared__ int   rb_s[TILE];                          // per-position row base (floats), same for K & V
    __shared__ float red_s[ROWS][8];
    __shared__ float m_s[ROWS], l_s[ROWS], alpha_s[ROWS];

    const int tid  = threadIdx.x;
    const int lane = tid & 31;
    const int wid  = tid >> 5;
    const int bh   = blockIdx.x;
    const int b    = bh >> 3;     // / HKV
    const int h    = bh & 7;      // % HKV

    // ---- load Q tile: rows r = g*QL + qi ----
    #pragma unroll
    for (int idx = tid; idx < ROWS * D_; idx += NTHREADS) {
        int r = idx >> 7, d = idx & 127;
        int g = r >> 2, qi = r & 3;
        Q_s[r][d] = query[(size_t)(b * QL + qi) * (HQ * D_) + (h * G_ + g) * D_ + d];
    }
    if (tid < ROWS) { m_s[tid] = -1e30f; l_s[tid] = 0.0f; }

    u64 o64[4] = {0ull, 0ull, 0ull, 0ull};   // 4 rows x 2 dims fp32 accumulator
    const int rg = tid >> 6;                  // row group 0..3 -> rows 4*rg..4*rg+3
    const int d2 = (tid & 63) * 2;            // dim pair
    const int* btrow = btab + b * (KVLEN / 16);

    __syncthreads();

    const float scale = 0.08838834764831845f;  // 1/sqrt(128)

    for (int t = 0; t < NTILES; t++) {
        const int base = t * TILE;

        // ================= phase 1: scores (thread <-> kv position) =================
        const int ki = base + tid;
        int rbase; const float* ksrc;
        if (ki >= BOUND) {
            rbase = (b * QL + (ki - BOUND)) * (HKV * D_) + h * D_;
            ksrc  = keyn;
        } else {
            int bt = btrow[ki >> 4];
            rbase = (bt * 16 + (ki & 15)) * (HKV * D_) + h * D_;
            ksrc  = kcache;
        }
        rb_s[tid] = rbase;   // reused by PV (same layout for value/value_cache)

        u64 acc[ROWS];
        #pragma unroll
        for (int r = 0; r < ROWS; r++) acc[r] = 0ull;

        const ulonglong2* kp = reinterpret_cast<const ulonglong2*>(ksrc + rbase);
        #pragma unroll 4
        for (int c = 0; c < 32; c++) {
            ulonglong2 k2 = kp[c];   // 4 floats of this kv row
            #pragma unroll
            for (int r = 0; r < ROWS; r++) {
                ulonglong2 q2 = *reinterpret_cast<const ulonglong2*>(&Q_s[r][c * 4]); // broadcast LDS.128
                fma2(acc[r], q2.x, k2.x);
                fma2(acc[r], q2.y, k2.y);
            }
        }

        float s[ROWS];
        #pragma unroll
        for (int r = 0; r < ROWS; r++) {
            float2 a = u2f(acc[r]);
            s[r] = (a.x + a.y) * scale;
            if (ki - (r & 3) > BOUND) s[r] = -1e30f;   // causal mask (qi = r & 3)
        }

        // ================= phase 2: online softmax =================
        // tile max per row
        #pragma unroll
        for (int r = 0; r < ROWS; r++) {
            float v = s[r];
            v = fmaxf(v, __shfl_xor_sync(0xffffffffu, v, 16));
            v = fmaxf(v, __shfl_xor_sync(0xffffffffu, v, 8));
            v = fmaxf(v, __shfl_xor_sync(0xffffffffu, v, 4));
            v = fmaxf(v, __shfl_xor_sync(0xffffffffu, v, 2));
            v = fmaxf(v, __shfl_xor_sync(0xffffffffu, v, 1));
            if (lane == 0) red_s[r][wid] = v;
        }
        __syncthreads();   // S1
        if (tid < ROWS) {
            float tm = red_s[tid][0];
            #pragma unroll
            for (int w = 1; w < 8; w++) tm = fmaxf(tm, red_s[tid][w]);
            float mo = m_s[tid];
            float mn = fmaxf(mo, tm);
            alpha_s[tid] = __expf(mo - mn);   // 0 on first tile
            m_s[tid] = mn;
        }
        __syncthreads();   // S2

        // p = exp(s - m_new); stage into shared, accumulate sums
        #pragma unroll
        for (int r = 0; r < ROWS; r += 4) {
            float4 p;
            p.x = __expf(s[r + 0] - m_s[r + 0]);
            p.y = __expf(s[r + 1] - m_s[r + 1]);
            p.z = __expf(s[r + 2] - m_s[r + 2]);
            p.w = __expf(s[r + 3] - m_s[r + 3]);
            *reinterpret_cast<float4*>(&P_s[tid][r]) = p;
            s[r + 0] = p.x; s[r + 1] = p.y; s[r + 2] = p.z; s[r + 3] = p.w;
        }
        #pragma unroll
        for (int r = 0; r < ROWS; r++) {
            float v = s[r];
            v += __shfl_xor_sync(0xffffffffu, v, 16);
            v += __shfl_xor_sync(0xffffffffu, v, 8);
            v += __shfl_xor_sync(0xffffffffu, v, 4);
            v += __shfl_xor_sync(0xffffffffu, v, 2);
            v += __shfl_xor_sync(0xffffffffu, v, 1);
            if (lane == 0) red_s[r][wid] = v;
        }
        __syncthreads();   // S3
        if (tid < ROWS) {
            float ts = red_s[tid][0];
            #pragma unroll
            for (int w = 1; w < 8; w++) ts += red_s[tid][w];
            l_s[tid] = l_s[tid] * alpha_s[tid] + ts;
        }

        // ================= phase 3: O += P * V (thread <-> 4 rows x 2 dims) =================
        #pragma unroll
        for (int rr = 0; rr < 4; rr++) {
            float a = alpha_s[rg * 4 + rr];
            float2 o = u2f(o64[rr]);
            o64[rr] = f2u(o.x * a, o.y * a);
        }

        if (base + TILE <= BOUND) {
            // fast path: whole tile from value_cache
            #pragma unroll 4
            for (int jj = 0; jj < TILE; jj++) {
                int rb = rb_s[jj];
                u64 v2 = *reinterpret_cast<const u64*>(vcache + rb + d2);
                float4 p4 = *reinterpret_cast<const float4*>(&P_s[jj][rg * 4]);
                fma2(o64[0], f2u(p4.x, p4.x), v2);
                fma2(o64[1], f2u(p4.y, p4.y), v2);
                fma2(o64[2], f2u(p4.z, p4.z), v2);
                fma2(o64[3], f2u(p4.w, p4.w), v2);
            }
        } else {
            // boundary tile: last QL positions come from new value tensor
            for (int jj = 0; jj < TILE; jj++) {
                int rb = rb_s[jj];
                const float* vsrc = (base + jj >= BOUND) ? valn : vcache;
                u64 v2 = *reinterpret_cast<const u64*>(vsrc + rb + d2);
                float4 p4 = *reinterpret_cast<const float4*>(&P_s[jj][rg * 4]);
                fma2(o64[0], f2u(p4.x, p4.x), v2);
                fma2(o64[1], f2u(p4.y, p4.y), v2);
                fma2(o64[2], f2u(p4.z, p4.z), v2);
                fma2(o64[3], f2u(p4.w, p4.w), v2);
            }
        }
        __syncthreads();   // S4: protect rb_s/P_s/red_s before next tile rewrites
    }

    // ================= epilogue: normalize and store =================
    #pragma unroll
    for (int rr = 0; rr < 4; rr++) {
        int r = rg * 4 + rr;
        float inv = 1.0f / l_s[r];
        float2 o = u2f(o64[rr]);
        int g = r >> 2, qi = r & 3;
        float2 res = make_float2(o.x * inv, o.y * inv);
        *reinterpret_cast<float2*>(out + (size_t)(b * QL + qi) * (HQ * D_)
                                       + (h * G_ + g) * D_ + d2) = res;
    }
}

extern "C" void kernel_launch(void* const* d_in, const int* in_sizes, int n_in,
                              void* d_out, int out_size) {
    (void)in_sizes; (void)n_in; (void)out_size;
    const float* query       = (const float*)d_in[0];
    const float* key_new     = (const float*)d_in[1];
    const float* value_new   = (const float*)d_in[2];
    const float* key_cache   = (const float*)d_in[3];
    const float* value_cache = (const float*)d_in[4];
    const int*   block_tables= (const int*)  d_in[5];
    // d_in[6] (new_cache_slots) is implied by structure: last QL positions of each sequence.

    attn_decode_kernel<<<B_ * HKV, NTHREADS>>>(query, key_new, value_new,
                                               key_cache, value_cache,
                                               block_tables, (float*)d_out);
}